// round 2
// baseline (speedup 1.0000x reference)
#include <cuda_runtime.h>
#include <cstdint>

#define NPIX 9216            // H*W = 96*96
#define BATCH 2
#define TOT (BATCH*NPIX)     // 18432
#define RPB 8                // attention rows per block

__device__ float g_p[TOT];   // channel-0 softmax per pixel (scratch)

typedef unsigned long long u64;

// ---- packed f32x2 helpers (FFMA2 path: only reachable via PTX) ----
__device__ __forceinline__ u64 pk2(float lo, float hi) {
    u64 r;
    asm("mov.b64 %0, {%1,%2};" : "=l"(r)
        : "r"(__float_as_uint(lo)), "r"(__float_as_uint(hi)));
    return r;
}
__device__ __forceinline__ void upk2(u64 v, float& lo, float& hi) {
    unsigned a, b;
    asm("mov.b64 {%0,%1}, %2;" : "=r"(a), "=r"(b) : "l"(v));
    lo = __uint_as_float(a); hi = __uint_as_float(b);
}
__device__ __forceinline__ u64 fma2(u64 a, u64 b, u64 c) {
    u64 d;
    asm("fma.rn.f32x2 %0, %1, %2, %3;" : "=l"(d) : "l"(a), "l"(b), "l"(c));
    return d;
}
__device__ __forceinline__ u64 mul2(u64 a, u64 b) {
    u64 d;
    asm("mul.rn.f32x2 %0, %1, %2;" : "=l"(d) : "l"(a), "l"(b));
    return d;
}
__device__ __forceinline__ u64 add2(u64 a, u64 b) {
    u64 d;
    asm("add.rn.f32x2 %0, %1, %2;" : "=l"(d) : "l"(a), "l"(b));
    return d;
}

// Kernel 1: p[b,n] = sigmoid(x0 - x1)  (channel softmax with C=2)
__global__ void k_prep(const float* __restrict__ x) {
    int i = blockIdx.x * blockDim.x + threadIdx.x;
    if (i >= TOT) return;
    int b = i / NPIX;
    int n = i - b * NPIX;
    float x0 = x[(size_t)(b * 2 + 0) * NPIX + n];
    float x1 = x[(size_t)(b * 2 + 1) * NPIX + n];
    g_p[i] = 1.0f / (1.0f + __expf(x1 - x0));
}

// Kernel 2: each block produces RPB attention rows + their y epilogue values.
//   e_m = exp(a_r * p_m)  (deg-6 Taylor, arg in (-1,1))
//   attn[row,m] = e_m / S ;  y[row] = sigmoid(conv(gamma*out + xs))
__global__ void __launch_bounds__(256, 2)
k_attn(const float* __restrict__ w, const float* __restrict__ cb,
       const float* __restrict__ gm,
       float* __restrict__ y, float* __restrict__ attn) {
    const int tid = threadIdx.x;
    const int lane = tid & 31, wid = tid >> 5;
    const int rowBase = blockIdx.x * RPB;          // never straddles batch (9216 % 8 == 0)
    const int b = rowBase / NPIX;

    // Load the p tile ONCE into registers (36 floats = 18 packed pairs / thread)
    const float4* __restrict__ p4 = reinterpret_cast<const float4*>(g_p + b * NPIX);
    u64 P[18];
#pragma unroll
    for (int k = 0; k < 9; k++) {
        float4 v = p4[tid + k * 256];
        P[2 * k + 0] = pk2(v.x, v.y);
        P[2 * k + 1] = pk2(v.z, v.w);
    }

    float a[RPB];
#pragma unroll
    for (int r = 0; r < RPB; r++)
        a[r] = 2.0f * g_p[rowBase + r] - 1.0f;

    // packed Taylor coefficients
    const u64 C6 = pk2(1.0f/720.0f, 1.0f/720.0f);
    const u64 C5 = pk2(1.0f/120.0f, 1.0f/120.0f);
    const u64 C4 = pk2(1.0f/24.0f,  1.0f/24.0f);
    const u64 C3 = pk2(1.0f/6.0f,   1.0f/6.0f);
    const u64 C2 = pk2(0.5f, 0.5f);
    const u64 C1 = pk2(1.0f, 1.0f);

    __shared__ float sS[8], sT[8];

#pragma unroll 1
    for (int r = 0; r < RPB; r++) {
        const u64 a2 = pk2(a[r], a[r]);
        u64 E[18];
        u64 S2 = pk2(0.0f, 0.0f), T2 = S2;
#pragma unroll
        for (int j = 0; j < 18; j++) {
            u64 t = mul2(a2, P[j]);
            u64 e = fma2(C6, t, C5);
            e = fma2(e, t, C4);
            e = fma2(e, t, C3);
            e = fma2(e, t, C2);
            e = fma2(e, t, C1);
            e = fma2(e, t, C1);
            E[j] = e;
            S2 = add2(S2, e);
            T2 = fma2(P[j], e, T2);
        }
        float Sl, Sh, Tl, Th;
        upk2(S2, Sl, Sh); float S = Sl + Sh;
        upk2(T2, Tl, Th); float T = Tl + Th;
#pragma unroll
        for (int o = 16; o > 0; o >>= 1) {
            S += __shfl_xor_sync(0xFFFFFFFFu, S, o);
            T += __shfl_xor_sync(0xFFFFFFFFu, T, o);
        }
        __syncthreads();                    // previous row's smem reads complete
        if (lane == 0) { sS[wid] = S; sT[wid] = T; }
        __syncthreads();
        float St = sS[0] + sS[1] + sS[2] + sS[3] + sS[4] + sS[5] + sS[6] + sS[7];
        float invS = 1.0f / St;

        if (tid == 0) {                     // fused conv1x1+sigmoid epilogue
            float Tt = sT[0] + sT[1] + sT[2] + sT[3] + sT[4] + sT[5] + sT[6] + sT[7];
            float o0 = Tt * invS;
            float p  = g_p[rowBase + r];
            float g  = gm[0];
            float pre0 = fmaf(g, o0, p);
            float pre1 = fmaf(g, 1.0f - o0, 1.0f - p);
            float t = fmaf(w[0], pre0, fmaf(w[1], pre1, cb[0]));
            y[rowBase + r] = 1.0f / (1.0f + __expf(-t));
        }

        const u64 inv2 = pk2(invS, invS);
        float4* __restrict__ out4 =
            reinterpret_cast<float4*>(attn + (size_t)(rowBase + r) * NPIX);
#pragma unroll
        for (int k = 0; k < 9; k++) {
            u64 v0 = mul2(E[2 * k + 0], inv2);
            u64 v1 = mul2(E[2 * k + 1], inv2);
            float4 o;
            upk2(v0, o.x, o.y);
            upk2(v1, o.z, o.w);
            out4[tid + k * 256] = o;        // coalesced 128B streaming stores
        }
    }
}

extern "C" void kernel_launch(void* const* d_in, const int* in_sizes, int n_in,
                              void* d_out, int out_size) {
    const float* x  = (const float*)d_in[0];   // [2,2,96,96]
    const float* w  = (const float*)d_in[1];   // [2]
    const float* cb = (const float*)d_in[2];   // [1]
    const float* gm = (const float*)d_in[3];   // [1]
    float* out = (float*)d_out;                // [18432 y | 2*9216*9216 attn]

    k_prep<<<(TOT + 127) / 128, 128>>>(x);
    k_attn<<<TOT / RPB, 256>>>(w, cb, gm, out, out + TOT);
}

// round 3
// speedup vs baseline: 1.1126x; 1.1126x over previous
#include <cuda_runtime.h>
#include <cstdint>

#define NPIX 9216            // H*W = 96*96
#define BATCH 2
#define TOT (BATCH*NPIX)     // 18432
#define RPB 8                // attention rows per block

__device__ float g_p[TOT];   // p = sigmoid(x0-x1)   (channel-0 softmax)
__device__ float g_a[TOT];   // a = (2p-1)*log2(e)   (premultiplied row scale)

__device__ __forceinline__ float ex2(float x) {
    float r;
    asm("ex2.approx.ftz.f32 %0, %1;" : "=f"(r) : "f"(x));
    return r;
}

// Kernel 1: per-pixel prep
__global__ void k_prep(const float* __restrict__ x) {
    int i = blockIdx.x * blockDim.x + threadIdx.x;
    if (i >= TOT) return;
    int b = i / NPIX;
    int n = i - b * NPIX;
    float x0 = x[(size_t)(b * 2 + 0) * NPIX + n];
    float x1 = x[(size_t)(b * 2 + 1) * NPIX + n];
    float p = 1.0f / (1.0f + __expf(x1 - x0));
    g_p[i] = p;
    g_a[i] = (2.0f * p - 1.0f) * 1.4426950408889634f;  // log2(e)
}

// Kernel 2: RPB attention rows per block; p tile cached in smem.
//   e_m = 2^(a_r * p_m) ; attn[row,m] = e_m / S ; y[row] fused epilogue
__global__ void __launch_bounds__(256, 3)
k_attn(const float* __restrict__ w, const float* __restrict__ cb,
       const float* __restrict__ gm,
       float* __restrict__ y, float* __restrict__ attn) {
    const int tid = threadIdx.x;
    const int lane = tid & 31, wid = tid >> 5;
    const int rowBase = blockIdx.x * RPB;      // 9216 % RPB == 0: no batch straddle
    const int b = rowBase / NPIX;

    __shared__ __align__(16) float sp[NPIX];   // 36 KB p tile
    __shared__ float sS[8], sT[8];

    {   // load p tile once per block (L2-resident source, 36 KB)
        const float4* __restrict__ src = reinterpret_cast<const float4*>(g_p + b * NPIX);
        float4* dst = reinterpret_cast<float4*>(sp);
#pragma unroll
        for (int k = 0; k < 9; k++)
            dst[tid + k * 256] = src[tid + k * 256];
    }
    __syncthreads();

#pragma unroll 1
    for (int r = 0; r < RPB; r++) {
        const int row = rowBase + r;
        const float a2 = g_a[row];             // (2p_r-1)*log2e, L2 hit

        float E[36];
        float S = 0.0f, T = 0.0f;
        const float4* sp4 = reinterpret_cast<const float4*>(sp);
#pragma unroll
        for (int k = 0; k < 9; k++) {
            float4 pv = sp4[tid + k * 256];
            float e0 = ex2(a2 * pv.x);
            float e1 = ex2(a2 * pv.y);
            float e2 = ex2(a2 * pv.z);
            float e3 = ex2(a2 * pv.w);
            E[4*k+0] = e0; E[4*k+1] = e1; E[4*k+2] = e2; E[4*k+3] = e3;
            S += (e0 + e1) + (e2 + e3);
            T = fmaf(pv.x, e0, T);
            T = fmaf(pv.y, e1, T);
            T = fmaf(pv.z, e2, T);
            T = fmaf(pv.w, e3, T);
        }

        // block reduce S, T
#pragma unroll
        for (int o = 16; o > 0; o >>= 1) {
            S += __shfl_xor_sync(0xFFFFFFFFu, S, o);
            T += __shfl_xor_sync(0xFFFFFFFFu, T, o);
        }
        __syncthreads();                       // protect sS/sT across rows
        if (lane == 0) { sS[wid] = S; sT[wid] = T; }
        __syncthreads();
        float St = ((sS[0] + sS[1]) + (sS[2] + sS[3]))
                 + ((sS[4] + sS[5]) + (sS[6] + sS[7]));
        float invS = 1.0f / St;

        if (tid == 0) {                        // fused conv1x1 + sigmoid epilogue
            float Tt = ((sT[0] + sT[1]) + (sT[2] + sT[3]))
                     + ((sT[4] + sT[5]) + (sT[6] + sT[7]));
            float o0 = Tt * invS;
            float p  = sp[row - b * NPIX];
            float g  = gm[0];
            float pre0 = fmaf(g, o0, p);
            float pre1 = fmaf(g, 1.0f - o0, 1.0f - p);
            float t = fmaf(w[0], pre0, fmaf(w[1], pre1, cb[0]));
            y[row] = 1.0f / (1.0f + __expf(-t));
        }

        float4* __restrict__ out4 =
            reinterpret_cast<float4*>(attn + (size_t)row * NPIX);
#pragma unroll
        for (int k = 0; k < 9; k++) {
            float4 o;
            o.x = E[4*k+0] * invS;
            o.y = E[4*k+1] * invS;
            o.z = E[4*k+2] * invS;
            o.w = E[4*k+3] * invS;
            out4[tid + k * 256] = o;           // coalesced 128B streaming stores
        }
    }
}

extern "C" void kernel_launch(void* const* d_in, const int* in_sizes, int n_in,
                              void* d_out, int out_size) {
    const float* x  = (const float*)d_in[0];   // [2,2,96,96]
    const float* w  = (const float*)d_in[1];   // [2]
    const float* cb = (const float*)d_in[2];   // [1]
    const float* gm = (const float*)d_in[3];   // [1]
    float* out = (float*)d_out;                // [18432 y | 2*9216*9216 attn]

    k_prep<<<(TOT + 127) / 128, 128>>>(x);
    k_attn<<<TOT / RPB, 256>>>(w, cb, gm, out, out + TOT);
}